// round 12
// baseline (speedup 1.0000x reference)
#include <cuda_runtime.h>
#include <cuda_fp16.h>
#include <cstdint>

// Problem constants
#define BB 64
#define TT 256
#define DD 512
#define HH 1024
#define N4H 4096   // 4*H
#define MM (BB*TT) // 16384
#define GRID 128   // persistent CTAs (co-resident)

// ---------------- device scratch ----------------
__device__ __half g_x16[(size_t)MM * DD];
__device__ __half g_WxT[(size_t)N4H * DD];
__device__ __half g_WhT[(size_t)N4H * HH];
__device__ float  g_XWb[(size_t)MM * N4H];   // layout [T][B][4H]
__device__ __half g_h16[2][BB * HH];
__device__ int    g_flags[GRID * 32];        // 128B-padded per-CTA "steps done" flags

// ---------------- helpers ----------------
__device__ __forceinline__ float sigm(float x) { return 1.f / (1.f + __expf(-x)); }

__device__ __forceinline__ void mma16816(float* c,
                                         uint32_t a0, uint32_t a1, uint32_t a2, uint32_t a3,
                                         uint32_t b0, uint32_t b1) {
    asm volatile(
        "mma.sync.aligned.m16n8k16.row.col.f32.f16.f16.f32 "
        "{%0,%1,%2,%3}, {%4,%5,%6,%7}, {%8,%9}, {%0,%1,%2,%3};\n"
        : "+f"(c[0]), "+f"(c[1]), "+f"(c[2]), "+f"(c[3])
        : "r"(a0), "r"(a1), "r"(a2), "r"(a3), "r"(b0), "r"(b1));
}

__device__ __forceinline__ void ldsm4(uint32_t& r0, uint32_t& r1, uint32_t& r2, uint32_t& r3,
                                      uint32_t addr) {
    asm volatile("ldmatrix.sync.aligned.m8n8.x4.shared.b16 {%0,%1,%2,%3}, [%4];"
                 : "=r"(r0), "=r"(r1), "=r"(r2), "=r"(r3) : "r"(addr));
}

// ---------------- dummy (ncu alignment: lstm = global launch #6) -------------
__global__ void noop_kernel() {}

// ---------------- prep ----------------
__global__ void prep_kernel(const float* __restrict__ x,
                            const float* __restrict__ W,
                            float* __restrict__ out) {
    size_t i0 = (size_t)blockIdx.x * blockDim.x + threadIdx.x;
    size_t stride = (size_t)gridDim.x * blockDim.x;
    for (size_t i = i0; i < GRID * 32; i += stride)
        g_flags[i] = 0;
    for (size_t i = i0; i < (size_t)MM * DD; i += stride)
        g_x16[i] = __float2half(x[i]);
    for (size_t i = i0; i < (size_t)N4H * DD; i += stride) {
        size_t n = i >> 9, k = i & 511;
        g_WxT[i] = __float2half(W[k * N4H + n]);
    }
    for (size_t i = i0; i < (size_t)N4H * HH; i += stride) {
        size_t n = i >> 10, k = i & 1023;
        g_WhT[i] = __float2half(W[(DD + k) * N4H + n]);
    }
    for (size_t i = i0; i < (size_t)BB * HH; i += stride) {
        out[i] = 0.f;
        g_h16[0][i] = __float2half(0.f);
        g_h16[1][i] = __float2half(0.f);
    }
}

// ---------------- precompute XWb = x @ Wx + b, output [T][B][4H] --------------
__global__ __launch_bounds__(128) void gemm_x_kernel(const float* __restrict__ bias) {
    __shared__ __half As[2][64 * 72];
    __shared__ __half Bs[2][64 * 72];
    const int tid = threadIdx.x;
    const int w = tid >> 5, lane = tid & 31;
    const int g = lane >> 2, tig = lane & 3;
    const int mt = blockIdx.y, nt = blockIdx.x;
    const int mbase = mt * 64;
    const int cw = nt * 64 + w * 16;

    const uint32_t AsS = (uint32_t)__cvta_generic_to_shared(&As[0][0]);
    const uint32_t BsS = (uint32_t)__cvta_generic_to_shared(&Bs[0][0]);
    const int aoff = (lane & 15) * 144 + ((lane >> 4) << 4);
    const int boff = ((lane & 7) + ((lane >> 4) & 1) * 8) * 144 + ((lane >> 3) & 1) * 16;

    float acc[4][2][4];
#pragma unroll
    for (int a = 0; a < 4; a++)
#pragma unroll
        for (int bq = 0; bq < 2; bq++)
#pragma unroll
            for (int e = 0; e < 4; e++) acc[a][bq][e] = 0.f;

    auto stage = [&](int c, int buf) {
        int kc = c * 64;
#pragma unroll
        for (int i = 0; i < 4; i++) {
            int idx = tid + i * 128;
            int r = idx >> 3, c8 = idx & 7;
            uint32_t da = (uint32_t)__cvta_generic_to_shared(&As[buf][r * 72 + c8 * 8]);
            const void* sa = &g_x16[(size_t)(mbase + r) * DD + kc + c8 * 8];
            asm volatile("cp.async.cg.shared.global [%0], [%1], 16;\n" :: "r"(da), "l"(sa));
            uint32_t db = (uint32_t)__cvta_generic_to_shared(&Bs[buf][r * 72 + c8 * 8]);
            const void* sb = &g_WxT[(size_t)(nt * 64 + r) * DD + kc + c8 * 8];
            asm volatile("cp.async.cg.shared.global [%0], [%1], 16;\n" :: "r"(db), "l"(sb));
        }
        asm volatile("cp.async.commit_group;\n" ::: "memory");
    };

    stage(0, 0);
    for (int c = 0; c < 8; c++) {
        __syncthreads();
        if (c < 7) {
            stage(c + 1, (c + 1) & 1);
            asm volatile("cp.async.wait_group 1;\n" ::: "memory");
        } else {
            asm volatile("cp.async.wait_group 0;\n" ::: "memory");
        }
        __syncthreads();
        const uint32_t Ab = AsS + (c & 1) * 9216;
        const uint32_t Bb = BsS + (c & 1) * 9216;
#pragma unroll
        for (int k0 = 0; k0 < 64; k0 += 16) {
            uint32_t b0, b1, b2, b3;
            ldsm4(b0, b1, b2, b3, Bb + w * 16 * 144 + k0 * 2 + boff);
#pragma unroll
            for (int mb = 0; mb < 4; mb++) {
                uint32_t a0, a1, a2, a3;
                ldsm4(a0, a1, a2, a3, Ab + mb * 2304 + k0 * 2 + aoff);
                mma16816(acc[mb][0], a0, a1, a2, a3, b0, b1);
                mma16816(acc[mb][1], a0, a1, a2, a3, b2, b3);
            }
        }
    }
#pragma unroll
    for (int mb = 0; mb < 4; mb++) {
#pragma unroll
        for (int nb = 0; nb < 2; nb++) {
            int col = cw + nb * 8 + 2 * tig;
            float2 bv = *(const float2*)&bias[col];
            int m0 = mbase + mb * 16 + g;
            int m1 = m0 + 8;
            size_t r0 = (size_t)((m0 & 255) * BB + (m0 >> 8));   // [t][b]
            size_t r1 = (size_t)((m1 & 255) * BB + (m1 >> 8));
            float2 v0 = {acc[mb][nb][0] + bv.x, acc[mb][nb][1] + bv.y};
            float2 v1 = {acc[mb][nb][2] + bv.x, acc[mb][nb][3] + bv.y};
            *(float2*)&g_XWb[r0 * N4H + col] = v0;
            *(float2*)&g_XWb[r1 * N4H + col] = v1;
        }
    }
}

// ---------------- persistent LSTM recurrence: producer-group dataflow sync ----
// 128 CTAs, 256 threads, split-K warps (gate gw = w&3, k-half kh = w>>2).
// SMEM: Wh_s 32 x 1032 halves (66048 B) | Hs 64 x 1032 halves (132096 B)
//       zs 2 x 2048 f32 (16384 B) | cs 512 f32 (2048 B)  -> total 216576 B
#define SM_WH   0
#define SM_HS   66048
#define SM_ZS   198144
#define SM_CS   214528
#define SM_TOT  216576

// Stage one k-quarter (256 k) of the 64x1024 h tile into Hs. 256 threads.
__device__ __forceinline__ void stage_quarter(char* smem_raw,
                                              const __half* __restrict__ hsrc,
                                              int q, int tid) {
    __half* dst = (__half*)(smem_raw + SM_HS);
    const int kq = q * 256;
#pragma unroll
    for (int i = 0; i < 8; i++) {
        int idx = tid + i * 256;        // 0..2047
        int r = idx >> 5;               // row 0..63
        int c8 = idx & 31;              // 16B unit within quarter
        uint32_t d = (uint32_t)__cvta_generic_to_shared(&dst[r * 1032 + kq + c8 * 8]);
        const void* s = &hsrc[r * HH + kq + c8 * 8];
        asm volatile("cp.async.cg.shared.global [%0], [%1], 16;\n" :: "r"(d), "l"(s));
    }
    asm volatile("cp.async.commit_group;\n" ::: "memory");
}

// Wait until the 32 producer CTAs of quarter q have published step >= t.
__device__ __forceinline__ void poll_group(int q, int t, int tid) {
    if (tid < 32) {
        int* f = &g_flags[(q * 32 + tid) * 32];
        int v;
        do {
            asm volatile("ld.acquire.gpu.global.s32 %0, [%1];"
                         : "=r"(v) : "l"(f) : "memory");
        } while (v < t);
    }
}

__global__ __launch_bounds__(256, 1) void lstm_persistent_kernel(
        const int* __restrict__ seq_len, float* __restrict__ out) {
    extern __shared__ char smem_raw[];
    __half* Wh_s = (__half*)(smem_raw + SM_WH);
    float*  zs   = (float*)(smem_raw + SM_ZS);
    float*  cs   = (float*)(smem_raw + SM_CS);

    const int tid = threadIdx.x;
    const int w = tid >> 5, lane = tid & 31;
    const int gw = w & 3, kh = w >> 2;        // gate, k-half
    const int g = lane >> 2, tig = lane & 3;
    const int j = blockIdx.x;                 // owns hidden units [8j, 8j+8)
    const int cw = gw * HH + j * 8;           // global gate-column base

    const uint32_t HsS = (uint32_t)__cvta_generic_to_shared(smem_raw + SM_HS);
    const int aoff = (lane & 15) * 2064 + ((lane >> 4) << 4);
    const __half* Bbase = &Wh_s[(gw * 8 + g) * 1032 + 2 * tig];

    // Load Wh slice: 32 local cols (gate*8+unit), padded stride 1032 halves
    for (int idx = tid; idx < 4096; idx += 256) {
        int lc = idx >> 7;
        int kk = (idx & 127) * 8;
        int gg = lc >> 3, u = lc & 7;
        size_t gcol = (size_t)gg * HH + j * 8 + u;
        *(int4*)&Wh_s[lc * 1032 + kk] = *(const int4*)&g_WhT[gcol * HH + kk];
    }
    for (int i = tid; i < 512; i += 256) cs[i] = 0.f;
    int slr[2];
#pragma unroll
    for (int s = 0; s < 2; s++) slr[s] = seq_len[(tid + s * 256) >> 3];
    int* my_flag = &g_flags[j * 32];
    __syncthreads();

    for (int t = 0; t < TT; t++) {
        const __half* __restrict__ h_read = g_h16[t & 1];
        __half* __restrict__ h_write = g_h16[(t + 1) & 1];

        float acc[4][4];
#pragma unroll
        for (int a = 0; a < 4; a++)
#pragma unroll
            for (int e = 0; e < 4; e++) acc[a][e] = 0.f;

        // kh=0 warps prefetch XWb epilogue operands (LDGs fly during polls)
        float2 xw[4][2];
        if (kh == 0) {
            const float* __restrict__ xwb_t = &g_XWb[(size_t)t * BB * N4H];
#pragma unroll
            for (int mb = 0; mb < 4; mb++) {
                int b0r = mb * 16 + g;
                xw[mb][0] = *(const float2*)&xwb_t[(size_t)b0r * N4H + cw + 2 * tig];
                xw[mb][1] = *(const float2*)&xwb_t[(size_t)(b0r + 8) * N4H + cw + 2 * tig];
            }
        } else {
#pragma unroll
            for (int mb = 0; mb < 4; mb++)
                xw[mb][0] = xw[mb][1] = make_float2(0.f, 0.f);
        }

        // MMA over one staged quarter (this warp's interleaved k-steps)
        auto mma_quarter = [&](int q) {
            const int kcq = q * 256 + kh * 16;
#pragma unroll
            for (int i = 0; i < 8; i++) {
                const int k0 = kcq + i * 32;
                uint32_t b0 = *(const uint32_t*)(Bbase + k0);
                uint32_t b1 = *(const uint32_t*)(Bbase + k0 + 8);
#pragma unroll
                for (int mb = 0; mb < 4; mb++) {
                    uint32_t a0, a1, a2, a3;
                    ldsm4(a0, a1, a2, a3, HsS + mb * 33024 + k0 * 2 + aoff);
                    mma16816(acc[mb], a0, a1, a2, a3, b0, b1);
                }
            }
        };

        // head: producers of q0/q1 ready -> stage q0/q1
        poll_group(0, t, tid); __syncthreads(); stage_quarter(smem_raw, h_read, 0, tid);
        poll_group(1, t, tid); __syncthreads(); stage_quarter(smem_raw, h_read, 1, tid);

        // q=0: (groups 0,1 committed) allow 1 pending -> q0 arrived
        asm volatile("cp.async.wait_group 1;\n" ::: "memory");
        __syncthreads();
        mma_quarter(0);
        poll_group(2, t, tid); __syncthreads(); stage_quarter(smem_raw, h_read, 2, tid);

        // q=1: (0,1,2 committed) allow 1 -> q1 arrived
        asm volatile("cp.async.wait_group 1;\n" ::: "memory");
        __syncthreads();
        mma_quarter(1);
        poll_group(3, t, tid); __syncthreads(); stage_quarter(smem_raw, h_read, 3, tid);

        // q=2: (0..3 committed) allow 1 -> q2 arrived
        asm volatile("cp.async.wait_group 1;\n" ::: "memory");
        __syncthreads();
        mma_quarter(2);

        // q=3
        asm volatile("cp.async.wait_group 0;\n" ::: "memory");
        __syncthreads();
        mma_quarter(3);

        // epilogue: partial z (+XWb for kh=0) -> zs[kh][gate][b][u]
        float* zsp = zs + kh * 2048;
#pragma unroll
        for (int mb = 0; mb < 4; mb++) {
            int b0r = mb * 16 + g;
            int u = 2 * tig;
            zsp[gw * 512 + b0r * 8 + u]           = acc[mb][0] + xw[mb][0].x;
            zsp[gw * 512 + b0r * 8 + u + 1]       = acc[mb][1] + xw[mb][0].y;
            zsp[gw * 512 + (b0r + 8) * 8 + u]     = acc[mb][2] + xw[mb][1].x;
            zsp[gw * 512 + (b0r + 8) * 8 + u + 1] = acc[mb][3] + xw[mb][1].y;
        }
        __syncthreads();

        // gates + state update (i, j, f, o; forget bias 1.0); 512 cells, 2/thread
#pragma unroll
        for (int s = 0; s < 2; s++) {
            int cell = tid + s * 256;
            int b = cell >> 3, u = cell & 7;
            int unit = j * 8 + u;
            float zi = zs[cell]        + zs[2048 + cell];
            float zj = zs[512 + cell]  + zs[2560 + cell];
            float zf = zs[1024 + cell] + zs[3072 + cell];
            float zo = zs[1536 + cell] + zs[3584 + cell];
            float c_old = cs[cell];
            float nc = c_old * sigm(zf + 1.0f) + sigm(zi) * tanhf(zj);
            float nh = tanhf(nc) * sigm(zo);
            bool act = t < slr[s];
            h_write[b * HH + unit] = act ? __float2half(nh) : h_read[b * HH + unit];
            if (act) {
                cs[cell] = nc;
                out[b * HH + unit] = nh;
            }
        }

        // publish: this CTA's h for step t is visible -> flag = t+1.
        // (No end-of-step barrier: next step's per-quarter producer polls are
        //  the synchronization. Groups 0-3 cover all CTAs, so staging step t
        //  implies all CTAs finished t-1 -> double-buffer WAR safety holds.)
        __syncthreads();   // all threads' h_write stores happen-before release
        if (tid == 0)
            asm volatile("st.release.gpu.global.s32 [%0], %1;"
                         :: "l"(my_flag), "r"(t + 1) : "memory");
    }
}

// ---------------- launch ----------------
extern "C" void kernel_launch(void* const* d_in, const int* in_sizes, int n_in,
                              void* d_out, int out_size) {
    const float* x = (const float*)d_in[0];
    const int* seq_len = (const int*)d_in[1];
    const float* W = (const float*)d_in[2];
    const float* bias = (const float*)d_in[3];
    float* out = (float*)d_out;

    cudaFuncSetAttribute(lstm_persistent_kernel,
                         cudaFuncAttributeMaxDynamicSharedMemorySize, SM_TOT);

    noop_kernel<<<1, 32>>>();   // keeps lstm at global launch #6 for ncu
    prep_kernel<<<8192, 256>>>(x, W, out);
    gemm_x_kernel<<<dim3(N4H / 64, MM / 64), 128>>>(bias);
    lstm_persistent_kernel<<<GRID, 256, SM_TOT>>>(seq_len, out);
}

// round 13
// speedup vs baseline: 1.3872x; 1.3872x over previous
#include <cuda_runtime.h>
#include <cuda_fp16.h>
#include <cstdint>

// Problem constants
#define BB 64
#define TT 256
#define DD 512
#define HH 1024
#define N4H 4096   // 4*H
#define MM (BB*TT) // 16384
#define GRID 128   // persistent CTAs (co-resident)

// ---------------- device scratch ----------------
__device__ __half g_x16[(size_t)MM * DD];
__device__ __half g_WxT[(size_t)N4H * DD];
__device__ __half g_WhT[(size_t)N4H * HH];
__device__ float  g_XWb[(size_t)MM * N4H];   // layout [T][B][4H]
__device__ __half g_h16[2][BB * HH];
__device__ int    g_flags[GRID * 32];        // 128B-padded per-CTA step flags

// ---------------- helpers ----------------
__device__ __forceinline__ float sigm(float x) { return 1.f / (1.f + __expf(-x)); }

__device__ __forceinline__ void mma16816(float* c,
                                         uint32_t a0, uint32_t a1, uint32_t a2, uint32_t a3,
                                         uint32_t b0, uint32_t b1) {
    asm volatile(
        "mma.sync.aligned.m16n8k16.row.col.f32.f16.f16.f32 "
        "{%0,%1,%2,%3}, {%4,%5,%6,%7}, {%8,%9}, {%0,%1,%2,%3};\n"
        : "+f"(c[0]), "+f"(c[1]), "+f"(c[2]), "+f"(c[3])
        : "r"(a0), "r"(a1), "r"(a2), "r"(a3), "r"(b0), "r"(b1));
}

__device__ __forceinline__ void ldsm4(uint32_t& r0, uint32_t& r1, uint32_t& r2, uint32_t& r3,
                                      uint32_t addr) {
    asm volatile("ldmatrix.sync.aligned.m8n8.x4.shared.b16 {%0,%1,%2,%3}, [%4];"
                 : "=r"(r0), "=r"(r1), "=r"(r2), "=r"(r3) : "r"(addr));
}

// ---------------- dummy (ncu alignment: lstm = global launch #6) -------------
__global__ void noop_kernel() {}

// ---------------- prep ----------------
__global__ void prep_kernel(const float* __restrict__ x,
                            const float* __restrict__ W,
                            float* __restrict__ out) {
    size_t i0 = (size_t)blockIdx.x * blockDim.x + threadIdx.x;
    size_t stride = (size_t)gridDim.x * blockDim.x;
    for (size_t i = i0; i < GRID * 32; i += stride)
        g_flags[i] = 0;
    for (size_t i = i0; i < (size_t)MM * DD; i += stride)
        g_x16[i] = __float2half(x[i]);
    for (size_t i = i0; i < (size_t)N4H * DD; i += stride) {
        size_t n = i >> 9, k = i & 511;
        g_WxT[i] = __float2half(W[k * N4H + n]);
    }
    for (size_t i = i0; i < (size_t)N4H * HH; i += stride) {
        size_t n = i >> 10, k = i & 1023;
        g_WhT[i] = __float2half(W[(DD + k) * N4H + n]);
    }
    for (size_t i = i0; i < (size_t)BB * HH; i += stride) {
        out[i] = 0.f;
        g_h16[0][i] = __float2half(0.f);
        g_h16[1][i] = __float2half(0.f);
    }
}

// ---------------- precompute XWb = x @ Wx + b, output [T][B][4H] --------------
__global__ __launch_bounds__(128) void gemm_x_kernel(const float* __restrict__ bias) {
    __shared__ __half As[2][64 * 72];
    __shared__ __half Bs[2][64 * 72];
    const int tid = threadIdx.x;
    const int w = tid >> 5, lane = tid & 31;
    const int g = lane >> 2, tig = lane & 3;
    const int mt = blockIdx.y, nt = blockIdx.x;
    const int mbase = mt * 64;
    const int cw = nt * 64 + w * 16;

    const uint32_t AsS = (uint32_t)__cvta_generic_to_shared(&As[0][0]);
    const uint32_t BsS = (uint32_t)__cvta_generic_to_shared(&Bs[0][0]);
    const int aoff = (lane & 15) * 144 + ((lane >> 4) << 4);
    const int boff = ((lane & 7) + ((lane >> 4) & 1) * 8) * 144 + ((lane >> 3) & 1) * 16;

    float acc[4][2][4];
#pragma unroll
    for (int a = 0; a < 4; a++)
#pragma unroll
        for (int bq = 0; bq < 2; bq++)
#pragma unroll
            for (int e = 0; e < 4; e++) acc[a][bq][e] = 0.f;

    auto stage = [&](int c, int buf) {
        int kc = c * 64;
#pragma unroll
        for (int i = 0; i < 4; i++) {
            int idx = tid + i * 128;
            int r = idx >> 3, c8 = idx & 7;
            uint32_t da = (uint32_t)__cvta_generic_to_shared(&As[buf][r * 72 + c8 * 8]);
            const void* sa = &g_x16[(size_t)(mbase + r) * DD + kc + c8 * 8];
            asm volatile("cp.async.cg.shared.global [%0], [%1], 16;\n" :: "r"(da), "l"(sa));
            uint32_t db = (uint32_t)__cvta_generic_to_shared(&Bs[buf][r * 72 + c8 * 8]);
            const void* sb = &g_WxT[(size_t)(nt * 64 + r) * DD + kc + c8 * 8];
            asm volatile("cp.async.cg.shared.global [%0], [%1], 16;\n" :: "r"(db), "l"(sb));
        }
        asm volatile("cp.async.commit_group;\n" ::: "memory");
    };

    stage(0, 0);
    for (int c = 0; c < 8; c++) {
        __syncthreads();
        if (c < 7) {
            stage(c + 1, (c + 1) & 1);
            asm volatile("cp.async.wait_group 1;\n" ::: "memory");
        } else {
            asm volatile("cp.async.wait_group 0;\n" ::: "memory");
        }
        __syncthreads();
        const uint32_t Ab = AsS + (c & 1) * 9216;
        const uint32_t Bb = BsS + (c & 1) * 9216;
#pragma unroll
        for (int k0 = 0; k0 < 64; k0 += 16) {
            uint32_t b0, b1, b2, b3;
            ldsm4(b0, b1, b2, b3, Bb + w * 16 * 144 + k0 * 2 + boff);
#pragma unroll
            for (int mb = 0; mb < 4; mb++) {
                uint32_t a0, a1, a2, a3;
                ldsm4(a0, a1, a2, a3, Ab + mb * 2304 + k0 * 2 + aoff);
                mma16816(acc[mb][0], a0, a1, a2, a3, b0, b1);
                mma16816(acc[mb][1], a0, a1, a2, a3, b2, b3);
            }
        }
    }
#pragma unroll
    for (int mb = 0; mb < 4; mb++) {
#pragma unroll
        for (int nb = 0; nb < 2; nb++) {
            int col = cw + nb * 8 + 2 * tig;
            float2 bv = *(const float2*)&bias[col];
            int m0 = mbase + mb * 16 + g;
            int m1 = m0 + 8;
            size_t r0 = (size_t)((m0 & 255) * BB + (m0 >> 8));   // [t][b]
            size_t r1 = (size_t)((m1 & 255) * BB + (m1 >> 8));
            float2 v0 = {acc[mb][nb][0] + bv.x, acc[mb][nb][1] + bv.y};
            float2 v1 = {acc[mb][nb][2] + bv.x, acc[mb][nb][3] + bv.y};
            *(float2*)&g_XWb[r0 * N4H + col] = v0;
            *(float2*)&g_XWb[r1 * N4H + col] = v1;
        }
    }
}

// ---------------- persistent LSTM recurrence: k-partitioned warps -------------
// 128 CTAs, 256 threads. Warp w owns k-eighth [128w, 128w+128), computes ALL
// 4 gates x 64 rows for it (each h byte read by ONE warp -> minimal crossbar).
// Each warp stages its own eighth (cp.async own-group wait + syncwarp: no
// cross-warp dependency until zs merge). Partial z merged pairwise (w <-> w+4)
// via named barriers into 4 fp32 copies; gates sum 4 copies.
// SMEM: Wh_s 32 x 1032 halves (66048) | Hs 8 x 16384 (131072, XOR-swizzled)
//       zs 4 x 2048 f32 (32768)  -> total 229888 B
#define SM_WH   0
#define SM_HS   66048
#define SM_ZS   197120
#define SM_TOT  229888

__global__ __launch_bounds__(256, 1) void lstm_persistent_kernel(
        const int* __restrict__ seq_len, float* __restrict__ out) {
    extern __shared__ char smem_raw[];
    __half* Wh_s = (__half*)(smem_raw + SM_WH);
    float*  zs   = (float*)(smem_raw + SM_ZS);

    const int tid = threadIdx.x;
    const int w = tid >> 5, lane = tid & 31;
    const int g = lane >> 2, tig = lane & 3;
    const int j = blockIdx.x;                 // owns hidden units [8j, 8j+8)
    const int r15 = lane & 15;
    const int hi16 = (lane >> 4) << 4;        // 0 or 16 (k vs k+8 halves)
    const int copy = w & 3;                   // zs copy / pair id

    const uint32_t wbuf = (uint32_t)__cvta_generic_to_shared(smem_raw + SM_HS) + w * 16384;

    // Load Wh slice: 32 local cols (gate*8+unit), padded stride 1032 halves
    for (int idx = tid; idx < 4096; idx += 256) {
        int lc = idx >> 7;
        int kk = (idx & 127) * 8;
        int gg = lc >> 3, u = lc & 7;
        size_t gcol = (size_t)gg * HH + j * 8 + u;
        *(int4*)&Wh_s[lc * 1032 + kk] = *(const int4*)&g_WhT[gcol * HH + kk];
    }
    // per-thread cell state + seq_len (cells tid, tid+256 fixed across steps)
    float cst[2] = {0.f, 0.f};
    int slr[2];
#pragma unroll
    for (int s = 0; s < 2; s++) slr[s] = seq_len[(tid + s * 256) >> 3];
    int* my_flag = &g_flags[j * 32];
    int* poll_flag = (tid < GRID) ? &g_flags[tid * 32] : nullptr;
    __syncthreads();

    for (int t = 0; t < TT; t++) {
        const __half* __restrict__ h_read = g_h16[t & 1];
        __half* __restrict__ h_write = g_h16[(t + 1) & 1];
        const __half* __restrict__ hsrc = h_read + w * 128;  // this warp's k-eighth

        // ---- stage own eighth: 64 rows x 256 B, XOR-swizzled, 2 groups ----
        // unit m = lane + 32*i: rows (lane>>4)+2i, u16 = lane&15 (coalesced 2 rows/instr)
#pragma unroll
        for (int i = 0; i < 16; i++) {       // group A: rows 0..31 (mb 0,1)
            int m = lane + 32 * i;
            int r = m >> 4, u16 = m & 15;
            uint32_t d = wbuf + r * 256 + ((u16 * 16) ^ ((r & 7) << 4));
            const void* s = &hsrc[(size_t)r * HH + u16 * 8];
            asm volatile("cp.async.cg.shared.global [%0], [%1], 16;\n" :: "r"(d), "l"(s));
        }
        asm volatile("cp.async.commit_group;\n" ::: "memory");
#pragma unroll
        for (int i = 16; i < 32; i++) {      // group B: rows 32..63 (mb 2,3)
            int m = lane + 32 * i;
            int r = m >> 4, u16 = m & 15;
            uint32_t d = wbuf + r * 256 + ((u16 * 16) ^ ((r & 7) << 4));
            const void* s = &hsrc[(size_t)r * HH + u16 * 8];
            asm volatile("cp.async.cg.shared.global [%0], [%1], 16;\n" :: "r"(d), "l"(s));
        }
        asm volatile("cp.async.commit_group;\n" ::: "memory");

        // ---- XWb prefetch for this thread's 2 gate cells (used at gate phase)
        float xwv[2][4];
#pragma unroll
        for (int s = 0; s < 2; s++) {
            int cell = tid + s * 256;
            int b = cell >> 3, u = cell & 7;
            const float* xp = &g_XWb[((size_t)t * BB + b) * N4H + j * 8 + u];
#pragma unroll
            for (int gg = 0; gg < 4; gg++) xwv[s][gg] = xp[gg * HH];
        }

        // ---- MMA: 8 ksteps x 4 gates x 4 mb, two row-half passes ----
        float acc[4][4][4];
#pragma unroll
        for (int a = 0; a < 4; a++)
#pragma unroll
            for (int n = 0; n < 4; n++)
#pragma unroll
                for (int e = 0; e < 4; e++) acc[a][n][e] = 0.f;

#pragma unroll
        for (int pass = 0; pass < 2; pass++) {
            if (pass == 0)
                asm volatile("cp.async.wait_group 1;\n" ::: "memory");
            else
                asm volatile("cp.async.wait_group 0;\n" ::: "memory");
            __syncwarp();
#pragma unroll
            for (int ks = 0; ks < 8; ks++) {
                const int k0 = w * 128 + ks * 16;       // global k (B index)
                uint32_t b0[4], b1[4];
#pragma unroll
                for (int nb = 0; nb < 4; nb++) {
                    const __half* bp = &Wh_s[(nb * 8 + g) * 1032 + k0 + 2 * tig];
                    b0[nb] = *(const uint32_t*)bp;
                    b1[nb] = *(const uint32_t*)(bp + 8);
                }
#pragma unroll
                for (int mbl = 0; mbl < 2; mbl++) {
                    const int mb = pass * 2 + mbl;
                    const int r = r15 + mb * 16;
                    uint32_t addr = wbuf + r * 256 + ((ks * 32 + hi16) ^ ((r & 7) << 4));
                    uint32_t a0, a1, a2, a3;
                    ldsm4(a0, a1, a2, a3, addr);
#pragma unroll
                    for (int nb = 0; nb < 4; nb++)
                        mma16816(acc[mb][nb], a0, a1, a2, a3, b0[nb], b1[nb]);
                }
            }
        }

        // ---- pairwise zs merge: warp w (>=4) writes raw, warp w-4 adds ----
        float* zc = zs + copy * 2048;
        if (w >= 4) {
#pragma unroll
            for (int mb = 0; mb < 4; mb++)
#pragma unroll
                for (int nb = 0; nb < 4; nb++) {
                    int b0r = mb * 16 + g;
                    int u = 2 * tig;
                    *(float2*)&zc[nb * 512 + b0r * 8 + u] =
                        make_float2(acc[mb][nb][0], acc[mb][nb][1]);
                    *(float2*)&zc[nb * 512 + (b0r + 8) * 8 + u] =
                        make_float2(acc[mb][nb][2], acc[mb][nb][3]);
                }
            asm volatile("bar.sync %0, 64;" :: "r"(copy + 1) : "memory");
        } else {
            asm volatile("bar.sync %0, 64;" :: "r"(copy + 1) : "memory");
#pragma unroll
            for (int mb = 0; mb < 4; mb++)
#pragma unroll
                for (int nb = 0; nb < 4; nb++) {
                    int b0r = mb * 16 + g;
                    int u = 2 * tig;
                    float2 p0 = *(const float2*)&zc[nb * 512 + b0r * 8 + u];
                    float2 p1 = *(const float2*)&zc[nb * 512 + (b0r + 8) * 8 + u];
                    *(float2*)&zc[nb * 512 + b0r * 8 + u] =
                        make_float2(acc[mb][nb][0] + p0.x, acc[mb][nb][1] + p0.y);
                    *(float2*)&zc[nb * 512 + (b0r + 8) * 8 + u] =
                        make_float2(acc[mb][nb][2] + p1.x, acc[mb][nb][3] + p1.y);
                }
        }
        __syncthreads();

        // ---- gates + state update (i, j, f, o; forget bias 1.0) ----
#pragma unroll
        for (int s = 0; s < 2; s++) {
            int cell = tid + s * 256;
            int b = cell >> 3, u = cell & 7;
            int unit = j * 8 + u;
            float zi = zs[cell]        + zs[2048 + cell]
                     + zs[4096 + cell] + zs[6144 + cell] + xwv[s][0];
            float zj = zs[512 + cell]  + zs[2560 + cell]
                     + zs[4608 + cell] + zs[6656 + cell] + xwv[s][1];
            float zf = zs[1024 + cell] + zs[3072 + cell]
                     + zs[5120 + cell] + zs[7168 + cell] + xwv[s][2];
            float zo = zs[1536 + cell] + zs[3584 + cell]
                     + zs[5632 + cell] + zs[7680 + cell] + xwv[s][3];
            float nc = cst[s] * sigm(zf + 1.0f) + sigm(zi) * tanhf(zj);
            float nh = tanhf(nc) * sigm(zo);
            bool act = t < slr[s];
            __half hp = h_read[b * HH + unit];
            h_write[b * HH + unit] = act ? __float2half(nh) : hp;
            if (act) {
                cst[s] = nc;
                out[b * HH + unit] = nh;
            }
        }

        // ---- distributed-flag device barrier (release/acquire, R10-proven) ----
        __syncthreads();   // all threads' h_write stores happen-before t0's release
        if (tid == 0)
            asm volatile("st.release.gpu.global.s32 [%0], %1;"
                         :: "l"(my_flag), "r"(t + 1) : "memory");
        if (tid < GRID) {
            int v;
            do {
                asm volatile("ld.acquire.gpu.global.s32 %0, [%1];"
                             : "=r"(v) : "l"(poll_flag) : "memory");
            } while (v < t + 1);
        }
        __syncthreads();   // acquirers' visibility propagates CTA-wide
    }
}

// ---------------- launch ----------------
extern "C" void kernel_launch(void* const* d_in, const int* in_sizes, int n_in,
                              void* d_out, int out_size) {
    const float* x = (const float*)d_in[0];
    const int* seq_len = (const int*)d_in[1];
    const float* W = (const float*)d_in[2];
    const float* bias = (const float*)d_in[3];
    float* out = (float*)d_out;

    cudaFuncSetAttribute(lstm_persistent_kernel,
                         cudaFuncAttributeMaxDynamicSharedMemorySize, SM_TOT);

    noop_kernel<<<1, 32>>>();   // keeps lstm at global launch #6 for ncu
    prep_kernel<<<8192, 256>>>(x, W, out);
    gemm_x_kernel<<<dim3(N4H / 64, MM / 64), 128>>>(bias);
    lstm_persistent_kernel<<<GRID, 256, SM_TOT>>>(seq_len, out);
}

// round 14
// speedup vs baseline: 1.5036x; 1.0839x over previous
#include <cuda_runtime.h>
#include <cuda_fp16.h>
#include <cstdint>

// Problem constants
#define BB 64
#define TT 256
#define DD 512
#define HH 1024
#define N4H 4096   // 4*H
#define MM (BB*TT) // 16384
#define GRID 128   // persistent CTAs (co-resident)

// ---------------- device scratch ----------------
__device__ __half g_x16[(size_t)MM * DD];
__device__ __half g_WxT[(size_t)N4H * DD];
__device__ __half g_WhT[(size_t)N4H * HH];
__device__ float  g_XWb[(size_t)MM * N4H];   // layout [T][B][4H]
__device__ __half g_h16[2][BB * HH];
__device__ int    g_flags[GRID * 32];        // 128B-padded per-CTA "steps done" flags

// ---------------- helpers ----------------
__device__ __forceinline__ float sigm(float x) { return 1.f / (1.f + __expf(-x)); }

__device__ __forceinline__ void mma16816(float* c,
                                         uint32_t a0, uint32_t a1, uint32_t a2, uint32_t a3,
                                         uint32_t b0, uint32_t b1) {
    asm volatile(
        "mma.sync.aligned.m16n8k16.row.col.f32.f16.f16.f32 "
        "{%0,%1,%2,%3}, {%4,%5,%6,%7}, {%8,%9}, {%0,%1,%2,%3};\n"
        : "+f"(c[0]), "+f"(c[1]), "+f"(c[2]), "+f"(c[3])
        : "r"(a0), "r"(a1), "r"(a2), "r"(a3), "r"(b0), "r"(b1));
}

__device__ __forceinline__ void ldsm4(uint32_t& r0, uint32_t& r1, uint32_t& r2, uint32_t& r3,
                                      uint32_t addr) {
    asm volatile("ldmatrix.sync.aligned.m8n8.x4.shared.b16 {%0,%1,%2,%3}, [%4];"
                 : "=r"(r0), "=r"(r1), "=r"(r2), "=r"(r3) : "r"(addr));
}

// ---------------- dummy (ncu alignment: lstm = global launch #6) -------------
__global__ void noop_kernel() {}

// ---------------- prep ----------------
__global__ void prep_kernel(const float* __restrict__ x,
                            const float* __restrict__ W,
                            float* __restrict__ out) {
    size_t i0 = (size_t)blockIdx.x * blockDim.x + threadIdx.x;
    size_t stride = (size_t)gridDim.x * blockDim.x;
    for (size_t i = i0; i < GRID * 32; i += stride)
        g_flags[i] = 0;
    for (size_t i = i0; i < (size_t)MM * DD; i += stride)
        g_x16[i] = __float2half(x[i]);
    for (size_t i = i0; i < (size_t)N4H * DD; i += stride) {
        size_t n = i >> 9, k = i & 511;
        g_WxT[i] = __float2half(W[k * N4H + n]);
    }
    for (size_t i = i0; i < (size_t)N4H * HH; i += stride) {
        size_t n = i >> 10, k = i & 1023;
        g_WhT[i] = __float2half(W[(DD + k) * N4H + n]);
    }
    for (size_t i = i0; i < (size_t)BB * HH; i += stride) {
        out[i] = 0.f;
        g_h16[0][i] = __float2half(0.f);
        g_h16[1][i] = __float2half(0.f);
    }
}

// ---------------- precompute XWb = x @ Wx + b, output [T][B][4H] --------------
__global__ __launch_bounds__(128) void gemm_x_kernel(const float* __restrict__ bias) {
    __shared__ __half As[2][64 * 72];
    __shared__ __half Bs[2][64 * 72];
    const int tid = threadIdx.x;
    const int w = tid >> 5, lane = tid & 31;
    const int g = lane >> 2, tig = lane & 3;
    const int mt = blockIdx.y, nt = blockIdx.x;
    const int mbase = mt * 64;
    const int cw = nt * 64 + w * 16;

    const uint32_t AsS = (uint32_t)__cvta_generic_to_shared(&As[0][0]);
    const uint32_t BsS = (uint32_t)__cvta_generic_to_shared(&Bs[0][0]);
    const int aoff = (lane & 15) * 144 + ((lane >> 4) << 4);
    const int boff = ((lane & 7) + ((lane >> 4) & 1) * 8) * 144 + ((lane >> 3) & 1) * 16;

    float acc[4][2][4];
#pragma unroll
    for (int a = 0; a < 4; a++)
#pragma unroll
        for (int bq = 0; bq < 2; bq++)
#pragma unroll
            for (int e = 0; e < 4; e++) acc[a][bq][e] = 0.f;

    auto stage = [&](int c, int buf) {
        int kc = c * 64;
#pragma unroll
        for (int i = 0; i < 4; i++) {
            int idx = tid + i * 128;
            int r = idx >> 3, c8 = idx & 7;
            uint32_t da = (uint32_t)__cvta_generic_to_shared(&As[buf][r * 72 + c8 * 8]);
            const void* sa = &g_x16[(size_t)(mbase + r) * DD + kc + c8 * 8];
            asm volatile("cp.async.cg.shared.global [%0], [%1], 16;\n" :: "r"(da), "l"(sa));
            uint32_t db = (uint32_t)__cvta_generic_to_shared(&Bs[buf][r * 72 + c8 * 8]);
            const void* sb = &g_WxT[(size_t)(nt * 64 + r) * DD + kc + c8 * 8];
            asm volatile("cp.async.cg.shared.global [%0], [%1], 16;\n" :: "r"(db), "l"(sb));
        }
        asm volatile("cp.async.commit_group;\n" ::: "memory");
    };

    stage(0, 0);
    for (int c = 0; c < 8; c++) {
        __syncthreads();
        if (c < 7) {
            stage(c + 1, (c + 1) & 1);
            asm volatile("cp.async.wait_group 1;\n" ::: "memory");
        } else {
            asm volatile("cp.async.wait_group 0;\n" ::: "memory");
        }
        __syncthreads();
        const uint32_t Ab = AsS + (c & 1) * 9216;
        const uint32_t Bb = BsS + (c & 1) * 9216;
#pragma unroll
        for (int k0 = 0; k0 < 64; k0 += 16) {
            uint32_t b0, b1, b2, b3;
            ldsm4(b0, b1, b2, b3, Bb + w * 16 * 144 + k0 * 2 + boff);
#pragma unroll
            for (int mb = 0; mb < 4; mb++) {
                uint32_t a0, a1, a2, a3;
                ldsm4(a0, a1, a2, a3, Ab + mb * 2304 + k0 * 2 + aoff);
                mma16816(acc[mb][0], a0, a1, a2, a3, b0, b1);
                mma16816(acc[mb][1], a0, a1, a2, a3, b2, b3);
            }
        }
    }
#pragma unroll
    for (int mb = 0; mb < 4; mb++) {
#pragma unroll
        for (int nb = 0; nb < 2; nb++) {
            int col = cw + nb * 8 + 2 * tig;
            float2 bv = *(const float2*)&bias[col];
            int m0 = mbase + mb * 16 + g;
            int m1 = m0 + 8;
            size_t r0 = (size_t)((m0 & 255) * BB + (m0 >> 8));   // [t][b]
            size_t r1 = (size_t)((m1 & 255) * BB + (m1 >> 8));
            float2 v0 = {acc[mb][nb][0] + bv.x, acc[mb][nb][1] + bv.y};
            float2 v1 = {acc[mb][nb][2] + bv.x, acc[mb][nb][3] + bv.y};
            *(float2*)&g_XWb[r0 * N4H + col] = v0;
            *(float2*)&g_XWb[r1 * N4H + col] = v1;
        }
    }
}

// ---------------- persistent LSTM recurrence: k-partitioned warps + dataflow --
// Warp w owns k-eighth [128w,128w+128) = h units from producer CTAs [16w,16w+16).
// Each warp: poll its 16 producers (parallel lanes) -> stage own eighth ->
// MMA all 4 gates x 64 rows. No CTA-wide sync until zs merge. Global barrier
// replaced by transitive producer polling (8 warps' producer sets cover all
// 128 CTAs; gates run post-__syncthreads => after all CTAs observed >= t).
// SMEM: Wh_s 32 x 1032 halves (66048) | Hs 8 x 16384 (131072, XOR-swizzled)
//       zs 4 x 2048 f32 (32768)  -> total 229888 B
#define SM_WH   0
#define SM_HS   66048
#define SM_ZS   197120
#define SM_TOT  229888

__global__ __launch_bounds__(256, 1) void lstm_persistent_kernel(
        const int* __restrict__ seq_len, float* __restrict__ out) {
    extern __shared__ char smem_raw[];
    __half* Wh_s = (__half*)(smem_raw + SM_WH);
    float*  zs   = (float*)(smem_raw + SM_ZS);

    const int tid = threadIdx.x;
    const int w = tid >> 5, lane = tid & 31;
    const int g = lane >> 2, tig = lane & 3;
    const int j = blockIdx.x;                 // owns hidden units [8j, 8j+8)
    const int r15 = lane & 15;
    const int hi16 = (lane >> 4) << 4;        // 0 or 16 (k vs k+8 halves)
    const int copy = w & 3;                   // zs copy / pair id

    const uint32_t wbuf = (uint32_t)__cvta_generic_to_shared(smem_raw + SM_HS) + w * 16384;

    // Load Wh slice: 32 local cols (gate*8+unit), padded stride 1032 halves
    for (int idx = tid; idx < 4096; idx += 256) {
        int lc = idx >> 7;
        int kk = (idx & 127) * 8;
        int gg = lc >> 3, u = lc & 7;
        size_t gcol = (size_t)gg * HH + j * 8 + u;
        *(int4*)&Wh_s[lc * 1032 + kk] = *(const int4*)&g_WhT[gcol * HH + kk];
    }
    // per-thread cell state + seq_len (cells tid, tid+256 fixed across steps)
    float cst[2] = {0.f, 0.f};
    int slr[2];
#pragma unroll
    for (int s = 0; s < 2; s++) slr[s] = seq_len[(tid + s * 256) >> 3];
    int* my_flag = &g_flags[j * 32];
    // warp w's producer flag (lanes 0-15 poll CTAs 16w .. 16w+15)
    int* prod_flag = (lane < 16) ? &g_flags[(w * 16 + lane) * 32] : nullptr;
    __syncthreads();

    for (int t = 0; t < TT; t++) {
        const __half* __restrict__ h_read = g_h16[t & 1];
        __half* __restrict__ h_write = g_h16[(t + 1) & 1];
        const __half* __restrict__ hsrc = h_read + w * 128;  // this warp's k-eighth

        // ---- XWb prefetch first (independent of h: LDGs fly during the poll)
        float xwv[2][4];
#pragma unroll
        for (int s = 0; s < 2; s++) {
            int cell = tid + s * 256;
            int b = cell >> 3, u = cell & 7;
            const float* xp = &g_XWb[((size_t)t * BB + b) * N4H + j * 8 + u];
#pragma unroll
            for (int gg = 0; gg < 4; gg++) xwv[s][gg] = xp[gg * HH];
        }

        // ---- per-warp producer poll: wait until 16 producers published step t
        if (lane < 16) {
            int v;
            do {
                asm volatile("ld.acquire.gpu.global.s32 %0, [%1];"
                             : "=r"(v) : "l"(prod_flag) : "memory");
            } while (v < t);
        }
        __syncwarp();

        // ---- stage own eighth: 64 rows x 256 B, XOR-swizzled, 2 groups ----
#pragma unroll
        for (int i = 0; i < 16; i++) {       // group A: rows 0..31 (mb 0,1)
            int m = lane + 32 * i;
            int r = m >> 4, u16 = m & 15;
            uint32_t d = wbuf + r * 256 + ((u16 * 16) ^ ((r & 7) << 4));
            const void* s = &hsrc[(size_t)r * HH + u16 * 8];
            asm volatile("cp.async.cg.shared.global [%0], [%1], 16;\n" :: "r"(d), "l"(s));
        }
        asm volatile("cp.async.commit_group;\n" ::: "memory");
#pragma unroll
        for (int i = 16; i < 32; i++) {      // group B: rows 32..63 (mb 2,3)
            int m = lane + 32 * i;
            int r = m >> 4, u16 = m & 15;
            uint32_t d = wbuf + r * 256 + ((u16 * 16) ^ ((r & 7) << 4));
            const void* s = &hsrc[(size_t)r * HH + u16 * 8];
            asm volatile("cp.async.cg.shared.global [%0], [%1], 16;\n" :: "r"(d), "l"(s));
        }
        asm volatile("cp.async.commit_group;\n" ::: "memory");

        // ---- MMA: 8 ksteps x 4 gates x 4 mb, two row-half passes ----
        float acc[4][4][4];
#pragma unroll
        for (int a = 0; a < 4; a++)
#pragma unroll
            for (int n = 0; n < 4; n++)
#pragma unroll
                for (int e = 0; e < 4; e++) acc[a][n][e] = 0.f;

#pragma unroll
        for (int pass = 0; pass < 2; pass++) {
            if (pass == 0)
                asm volatile("cp.async.wait_group 1;\n" ::: "memory");
            else
                asm volatile("cp.async.wait_group 0;\n" ::: "memory");
            __syncwarp();
#pragma unroll
            for (int ks = 0; ks < 8; ks++) {
                const int k0 = w * 128 + ks * 16;       // global k (B index)
                uint32_t b0[4], b1[4];
#pragma unroll
                for (int nb = 0; nb < 4; nb++) {
                    const __half* bp = &Wh_s[(nb * 8 + g) * 1032 + k0 + 2 * tig];
                    b0[nb] = *(const uint32_t*)bp;
                    b1[nb] = *(const uint32_t*)(bp + 8);
                }
#pragma unroll
                for (int mbl = 0; mbl < 2; mbl++) {
                    const int mb = pass * 2 + mbl;
                    const int r = r15 + mb * 16;
                    uint32_t addr = wbuf + r * 256 + ((ks * 32 + hi16) ^ ((r & 7) << 4));
                    uint32_t a0, a1, a2, a3;
                    ldsm4(a0, a1, a2, a3, addr);
#pragma unroll
                    for (int nb = 0; nb < 4; nb++)
                        mma16816(acc[mb][nb], a0, a1, a2, a3, b0[nb], b1[nb]);
                }
            }
        }

        // ---- pairwise zs merge: warp w (>=4) writes raw, warp w-4 adds ----
        float* zc = zs + copy * 2048;
        if (w >= 4) {
#pragma unroll
            for (int mb = 0; mb < 4; mb++)
#pragma unroll
                for (int nb = 0; nb < 4; nb++) {
                    int b0r = mb * 16 + g;
                    int u = 2 * tig;
                    *(float2*)&zc[nb * 512 + b0r * 8 + u] =
                        make_float2(acc[mb][nb][0], acc[mb][nb][1]);
                    *(float2*)&zc[nb * 512 + (b0r + 8) * 8 + u] =
                        make_float2(acc[mb][nb][2], acc[mb][nb][3]);
                }
            asm volatile("bar.sync %0, 64;" :: "r"(copy + 1) : "memory");
        } else {
            asm volatile("bar.sync %0, 64;" :: "r"(copy + 1) : "memory");
#pragma unroll
            for (int mb = 0; mb < 4; mb++)
#pragma unroll
                for (int nb = 0; nb < 4; nb++) {
                    int b0r = mb * 16 + g;
                    int u = 2 * tig;
                    float2 p0 = *(const float2*)&zc[nb * 512 + b0r * 8 + u];
                    float2 p1 = *(const float2*)&zc[nb * 512 + (b0r + 8) * 8 + u];
                    *(float2*)&zc[nb * 512 + b0r * 8 + u] =
                        make_float2(acc[mb][nb][0] + p0.x, acc[mb][nb][1] + p0.y);
                    *(float2*)&zc[nb * 512 + (b0r + 8) * 8 + u] =
                        make_float2(acc[mb][nb][2] + p1.x, acc[mb][nb][3] + p1.y);
                }
        }
        __syncthreads();   // all warps' polls passed + zs merged

        // ---- gates + state update (i, j, f, o; forget bias 1.0) ----
        float nhv[2];
        bool actv[2];
#pragma unroll
        for (int s = 0; s < 2; s++) {
            int cell = tid + s * 256;
            int b = cell >> 3, u = cell & 7;
            int unit = j * 8 + u;
            float zi = zs[cell]        + zs[2048 + cell]
                     + zs[4096 + cell] + zs[6144 + cell] + xwv[s][0];
            float zj = zs[512 + cell]  + zs[2560 + cell]
                     + zs[4608 + cell] + zs[6656 + cell] + xwv[s][1];
            float zf = zs[1024 + cell] + zs[3072 + cell]
                     + zs[5120 + cell] + zs[7168 + cell] + xwv[s][2];
            float zo = zs[1536 + cell] + zs[3584 + cell]
                     + zs[5632 + cell] + zs[7680 + cell] + xwv[s][3];
            float nc = cst[s] * sigm(zf + 1.0f) + sigm(zi) * tanhf(zj);
            float nh = tanhf(nc) * sigm(zo);
            bool act = t < slr[s];
            __half hp = h_read[b * HH + unit];
            h_write[b * HH + unit] = act ? __float2half(nh) : hp;
            if (act) cst[s] = nc;
            nhv[s] = nh;
            actv[s] = act;
        }

        // ---- publish h availability (release), then off-path out stores ----
        __syncthreads();   // all threads' h_write stores happen-before release
        if (tid == 0)
            asm volatile("st.release.gpu.global.s32 [%0], %1;"
                         :: "l"(my_flag), "r"(t + 1) : "memory");
#pragma unroll
        for (int s = 0; s < 2; s++) {
            if (actv[s]) {
                int cell = tid + s * 256;
                out[(cell >> 3) * HH + j * 8 + (cell & 7)] = nhv[s];
            }
        }
    }
}

// ---------------- launch ----------------
extern "C" void kernel_launch(void* const* d_in, const int* in_sizes, int n_in,
                              void* d_out, int out_size) {
    const float* x = (const float*)d_in[0];
    const int* seq_len = (const int*)d_in[1];
    const float* W = (const float*)d_in[2];
    const float* bias = (const float*)d_in[3];
    float* out = (float*)d_out;

    cudaFuncSetAttribute(lstm_persistent_kernel,
                         cudaFuncAttributeMaxDynamicSharedMemorySize, SM_TOT);

    noop_kernel<<<1, 32>>>();   // keeps lstm at global launch #6 for ncu
    prep_kernel<<<8192, 256>>>(x, W, out);
    gemm_x_kernel<<<dim3(N4H / 64, MM / 64), 128>>>(bias);
    lstm_persistent_kernel<<<GRID, 256, SM_TOT>>>(seq_len, out);
}